// round 15
// baseline (speedup 1.0000x reference)
#include <cuda_runtime.h>
#include <math.h>

// Problem dims
#define BATCH 512
#define TT    512
#define DD    128
#define HH    64

#define GE 256      // encoder gates 4H
#define KE 192      // encoder K = D + H
#define GD 512      // decoder gates 4D
#define KD 128      // decoder K = D

typedef unsigned long long u64t;

// ---------------- device scratch ----------------
__device__ __align__(16) float g_WeFrag[2 * 8 * 24 * 128];  // 49152: encoder Whh+Wih tf32 mma fragments
__device__ __align__(16) float g_WdFrag[2 * 16 * 16 * 128]; // 65536: decoder Whh tf32 mma fragments
__device__ __align__(16) float g_Wihd2[2 * HH * 256];       // 32768: decoder input proj [role][k][lrow]
__device__ __align__(16) float g_henc  [BATCH * HH];

// ---------------- helpers ----------------
__device__ __forceinline__ float tanh_ap(float x) {
    asm("tanh.approx.f32 %0, %0;" : "+f"(x)); return x;
}
__device__ __forceinline__ float sig_ap(float x) {
    return fmaf(tanh_ap(0.5f * x), 0.5f, 0.5f);
}
__device__ __forceinline__ unsigned tf32r(float f) {
    unsigned u; asm("cvt.rna.tf32.f32 %0, %1;" : "=r"(u) : "f"(f)); return u;
}
__device__ __forceinline__ float tf32f(float f) { return __uint_as_float(tf32r(f)); }
__device__ __forceinline__ void mma_tf32(float d[4],
                                         unsigned a0, unsigned a1, unsigned a2, unsigned a3,
                                         unsigned b0, unsigned b1) {
    asm volatile(
        "mma.sync.aligned.m16n8k8.row.col.f32.tf32.tf32.f32 "
        "{%0,%1,%2,%3}, {%4,%5,%6,%7}, {%8,%9}, {%0,%1,%2,%3};"
        : "+f"(d[0]), "+f"(d[1]), "+f"(d[2]), "+f"(d[3])
        : "r"(a0), "r"(a1), "r"(a2), "r"(a3), "r"(b0), "r"(b1));
}
#define CLUSTER_SYNC() do { \
    asm volatile("barrier.cluster.arrive.aligned;" ::: "memory"); \
    asm volatile("barrier.cluster.wait.aligned;" ::: "memory"); \
} while (0)

// local arrive (release.cta orders my shared::cta stores)
#define MBAR_ARRIVE_LOCAL(addr) \
    asm volatile("mbarrier.arrive.shared::cta.b64 _, [%0];" :: "r"(addr) : "memory")
// remote arrive on peer's mbarrier — RELEASE.CLUSTER orders my st.shared::cluster
// data stores at cluster scope before the arrival is observed (the R14 bug was
// the default .release.cta here).
#define MBAR_ARRIVE_REMOTE(addr) \
    asm volatile("mbarrier.arrive.release.cluster.shared::cluster.b64 _, [%0];" :: "r"(addr) : "memory")
// spin wait with acquire.cluster (observe peer DSMEM writes)
#define MBAR_WAIT_CLUSTER(addr, parity) do { \
    asm volatile( \
        "{\n\t.reg .pred P1;\n\t" \
        "WL_%=:\n\t" \
        "mbarrier.try_wait.parity.acquire.cluster.shared::cta.b64 P1, [%0], %1, 0x989680;\n\t" \
        "@P1 bra.uni WD_%=;\n\t" \
        "bra.uni WL_%=;\n\t" \
        "WD_%=:\n\t}" \
        :: "r"(addr), "r"(parity) : "memory"); \
} while (0)

// ---------------- prep: build tf32 mma fragments (one-time, tiny) ----------------
__global__ void prep_kernel(const float* __restrict__ Wih_e,
                            const float* __restrict__ Whh_e,
                            const float* __restrict__ Whh_d,
                            const float* __restrict__ Wih_d) {
    int idx = blockIdx.x * 256 + threadIdx.x;            // 0 .. 147455
    if (idx < 49152) {                                   // encoder fragments
        int wblk = idx / 3072;                           // role*8 + w
        int rem  = idx - wblk * 3072;
        int kt = rem >> 7;                               // 0..23
        int r2 = rem & 127;
        int l = r2 >> 2, c = r2 & 3;
        int gr = l >> 2, gc = l & 3;
        int row = (wblk >> 3) * 128 + (wblk & 7) * 16 + gr + (c & 1) * 8;   // 0..255
        int k   = kt * 8 + gc + ((c >> 1) & 1) * 4;                          // 0..191
        float v = (k < DD) ? Wih_e[row * DD + k] : Whh_e[row * HH + (k - DD)];
        g_WeFrag[idx] = __uint_as_float(tf32r(v));
        return;
    }
    int f = idx - 49152;
    if (f < 65536) {                                     // decoder fragments (validated)
        int rw = f >> 11;
        int role = rw >> 4, w = rw & 15;
        int rem = f & 2047;
        int i4 = rem >> 7;
        int r2 = rem & 127;
        int l = r2 >> 2, c = r2 & 3;
        int gr = l >> 2, gc = l & 3;
        int lrow = w * 16 + gr + (c & 1) * 8;
        int k = i4 * 8 + gc + ((c >> 1) & 1) * 4;
        int gate = lrow >> 6, j = lrow & 63;
        int grow = gate * 128 + role * 64 + j;
        g_WdFrag[f] = __uint_as_float(tf32r(Whh_d[grow * 128 + k]));
        return;
    }
    int f2 = f - 65536;
    if (f2 < 32768) {                                    // decoder input proj [role][k][lrow]
        int rolek = f2 >> 8, lr = f2 & 255;
        int role = rolek >> 6, k = rolek & 63;
        int gate = lr >> 6, j = lr & 63;
        int grow = gate * 128 + role * 64 + j;
        g_Wihd2[f2] = Wih_d[grow * 64 + k];
    }
}

// ---------------- encoder: 2-CTA cluster, register-resident tf32 mma ----------------
// 64 clusters x 2 CTAs x 8 batches; 256 threads/CTA; CTA role r owns gate rows [r*128, r*128+128).
// SMEM floats: xs[8][132] 1056 | hs[2][8][72] 1152 | gsm[2][256][9] 4608 | mbar 2
#define EXS 0
#define EHS 1056
#define EGS 2208
#define EMB (EGS + 4608)
#define ENC_SMEM_F (EMB + 2)
#define ENC_SMEM_BYTES (ENC_SMEM_F * 4)

__global__ __launch_bounds__(256, 1) __cluster_dims__(2, 1, 1)
void enc_kernel(const float* __restrict__ x, const float* __restrict__ b_e) {
    extern __shared__ float sm[];
    float* xs  = sm + EXS;     // [b][132]   x_t staging (k contiguous)
    float* hs  = sm + EHS;     // [2][b][72] double-buffered hidden
    float* gsm = sm + EGS;     // [2][256 row][9 b] double-buffered gates

    const int tid = threadIdx.x;
    const int w = tid >> 5, l = tid & 31;
    const int gr = l >> 2, gc = l & 3;
    unsigned rank;
    asm("mov.u32 %0, %%cluster_ctarank;" : "=r"(rank));
    const int bb = (blockIdx.x >> 1) * 8;

    const unsigned smb = (unsigned)__cvta_generic_to_shared(sm);
    const unsigned mbar = smb + EMB * 4;
    if (tid == 0)
        asm volatile("mbarrier.init.shared.b64 [%0], %1;" :: "r"(mbar), "r"(512) : "memory");

    // A fragments: 24 k-tiles x float4, coalesced
    float4 af[24];
    {
        const float4* Asrc = (const float4*)g_WeFrag + ((int)rank * 8 + w) * 768;
        #pragma unroll
        for (int kt = 0; kt < 24; ++kt) af[kt] = Asrc[kt * 32 + l];
    }
    const int row0 = (int)rank * 128 + w * 16 + gr;      // global gate rows this thread owns
    const float bsr0 = b_e[row0], bsr1 = b_e[row0 + 8];

    // zero hidden buffers
    for (int i = tid; i < 1152; i += 256) hs[i] = 0.0f;

    // stage x_0 (tf32-rounded)
    const int xb = tid >> 5, xk = (tid & 31) * 4;
    {
        float4 v = *(const float4*)&x[(size_t)(bb + xb) * TT * DD + xk];
        float* d = &xs[xb * 132 + xk];
        d[0] = tf32f(v.x); d[1] = tf32f(v.y); d[2] = tf32f(v.z); d[3] = tf32f(v.w);
    }
    __syncthreads();
    CLUSTER_SYNC();            // mbarrier init + x0/h0 visible cluster-wide

    // remote bases (peer CTA)
    unsigned gU = (unsigned)__cvta_generic_to_shared(gsm);
    unsigned remG, remMbar;
    asm("mapa.shared::cluster.u32 %0, %1, %2;" : "=r"(remG) : "r"(gU), "r"(rank ^ 1u));
    asm("mapa.shared::cluster.u32 %0, %1, %2;" : "=r"(remMbar) : "r"(mbar), "r"(rank ^ 1u));

    const int ej = tid & 63, eb = tid >> 6;              // elementwise: (j, eb) and (j, eb+4)
    float c0 = 0.0f, c1 = 0.0f, h0 = 0.0f, h1 = 0.0f;

    for (int t = 0; t < TT; ++t) {
        // prefetch x_{t+1} early (consumed after the wait)
        float4 xn = make_float4(0.f, 0.f, 0.f, 0.f);
        if (t + 1 < TT)
            xn = *(const float4*)&x[(size_t)(bb + xb) * TT * DD + (size_t)(t + 1) * DD + xk];

        const int rb = (t & 1) ^ 1;                      // h read buffer
        const int wbuf = t & 1;                          // gate buffer for this step

        float dd[4] = {bsr0, bsr0, bsr1, bsr1};
        float ee[4] = {0.f, 0.f, 0.f, 0.f};
        // x part: kt 0..15
        #pragma unroll
        for (int kt = 0; kt < 16; ++kt) {
            float b0 = xs[gr * 132 + kt * 8 + gc];
            float b1 = xs[gr * 132 + kt * 8 + gc + 4];
            mma_tf32((kt & 1) ? ee : dd,
                     __float_as_uint(af[kt].x), __float_as_uint(af[kt].y),
                     __float_as_uint(af[kt].z), __float_as_uint(af[kt].w),
                     __float_as_uint(b0), __float_as_uint(b1));
        }
        // h part: kt 16..23
        #pragma unroll
        for (int kt = 16; kt < 24; ++kt) {
            int kk = (kt - 16) * 8;
            float b0 = hs[(rb * 8 + gr) * 72 + kk + gc];
            float b1 = hs[(rb * 8 + gr) * 72 + kk + gc + 4];
            mma_tf32((kt & 1) ? ee : dd,
                     __float_as_uint(af[kt].x), __float_as_uint(af[kt].y),
                     __float_as_uint(af[kt].z), __float_as_uint(af[kt].w),
                     __float_as_uint(b0), __float_as_uint(b1));
        }
        float g0 = dd[0] + ee[0], g1 = dd[1] + ee[1];
        float g2 = dd[2] + ee[2], g3 = dd[3] + ee[3];

        // store my gate block locally AND to peer (same offsets)
        {
            unsigned o0 = (unsigned)(((wbuf * 256 + row0) * 9 + 2 * gc) * 4);
            unsigned o1 = (unsigned)(((wbuf * 256 + row0 + 8) * 9 + 2 * gc) * 4);
            gsm[(wbuf * 256 + row0) * 9 + 2 * gc]         = g0;
            gsm[(wbuf * 256 + row0) * 9 + 2 * gc + 1]     = g1;
            gsm[(wbuf * 256 + row0 + 8) * 9 + 2 * gc]     = g2;
            gsm[(wbuf * 256 + row0 + 8) * 9 + 2 * gc + 1] = g3;
            asm volatile("st.shared::cluster.f32 [%0], %1;" :: "r"(remG + o0),     "f"(g0) : "memory");
            asm volatile("st.shared::cluster.f32 [%0], %1;" :: "r"(remG + o0 + 4), "f"(g1) : "memory");
            asm volatile("st.shared::cluster.f32 [%0], %1;" :: "r"(remG + o1),     "f"(g2) : "memory");
            asm volatile("st.shared::cluster.f32 [%0], %1;" :: "r"(remG + o1 + 4), "f"(g3) : "memory");
        }
        MBAR_ARRIVE_LOCAL(mbar);          // orders my local gsm stores
        MBAR_ARRIVE_REMOTE(remMbar);      // release.cluster: orders my DSMEM gate stores
        MBAR_WAIT_CLUSTER(mbar, (unsigned)(t & 1));   // all 256 local + 256 peer arrived

        // elementwise (both CTAs compute full h) — 2 cells per thread
        {
            const float* gb = gsm + wbuf * 256 * 9;
            float gi = gb[(ej)       * 9 + eb];
            float gf = gb[(64 + ej)  * 9 + eb];
            float gg = gb[(128 + ej) * 9 + eb];
            float go = gb[(192 + ej) * 9 + eb];
            float i_ = sig_ap(gi), f_ = sig_ap(gf), gv = tanh_ap(gg), o_ = sig_ap(go);
            c0 = f_ * c0 + i_ * gv;
            h0 = o_ * tanh_ap(c0);
            hs[(wbuf * 8 + eb) * 72 + ej] = tf32f(h0);

            gi = gb[(ej)       * 9 + eb + 4];
            gf = gb[(64 + ej)  * 9 + eb + 4];
            gg = gb[(128 + ej) * 9 + eb + 4];
            go = gb[(192 + ej) * 9 + eb + 4];
            i_ = sig_ap(gi); f_ = sig_ap(gf); gv = tanh_ap(gg); o_ = sig_ap(go);
            c1 = f_ * c1 + i_ * gv;
            h1 = o_ * tanh_ap(c1);
            hs[(wbuf * 8 + eb + 4) * 72 + ej] = tf32f(h1);
        }
        // commit x_{t+1} (safe: all local threads passed the wait => finished mma reads)
        {
            float* d = &xs[xb * 132 + xk];
            d[0] = tf32f(xn.x); d[1] = tf32f(xn.y); d[2] = tf32f(xn.z); d[3] = tf32f(xn.w);
        }
        __syncthreads();       // hs/xs writes visible before next step's mma
    }
    g_henc[(bb + eb) * HH + ej]     = h0;
    g_henc[(bb + eb + 4) * HH + ej] = h1;
    CLUSTER_SYNC();            // keep peer alive until both CTAs are done
}

// ---------------- decoder: cluster mma kernel, mbarrier h-exchange ----------------
// SMEM floats: hsm 2048 | xp 2048 | gsm 2560 | mbar 2
#define DMB 6656
#define DEC_SMEM_F (DMB + 2)
#define DEC_SMEM_BYTES (DEC_SMEM_F * 4)

__global__ __launch_bounds__(512, 1) __cluster_dims__(2, 1, 1)
void dec_kernel(const float* __restrict__ b_d, float* __restrict__ out) {
    extern __shared__ float sm[];
    float* hsm = sm;              // [2][128 k][8 b]
    float* xp  = sm + 2048;       // [256 lrow][8 b]
    float* gsm = sm + 4096;       // [256 lrow][10]
    float* hesm = gsm;            // reuse for h_enc staging

    const int tid = threadIdx.x;
    const int w = tid >> 5, l = tid & 31;
    unsigned rank;
    asm("mov.u32 %0, %%cluster_ctarank;" : "=r"(rank));
    const int bb   = (blockIdx.x >> 1) * 8;
    const int koff = (int)rank * 64;

    const unsigned smb = (unsigned)__cvta_generic_to_shared(sm);
    const unsigned mbar = smb + DMB * 4;
    if (tid == 0)
        asm volatile("mbarrier.init.shared.b64 [%0], %1;" :: "r"(mbar), "r"(1024) : "memory");

    float4 af[16];
    {
        const float4* Asrc = (const float4*)g_WdFrag + ((int)rank * 16 + w) * 512;
        #pragma unroll
        for (int i4 = 0; i4 < 16; ++i4) af[i4] = Asrc[i4 * 32 + l];
    }

    hsm[tid] = 0.0f; hsm[512 + tid] = 0.0f;
    hsm[1024 + tid] = 0.0f; hsm[1536 + tid] = 0.0f;
    hesm[tid] = g_henc[bb * 64 + tid];
    __syncthreads();

    {
        int lr = tid >> 1, b4 = (tid & 1) * 4;
        int gate = lr >> 6, j = lr & 63;
        int grow = gate * 128 + koff + j;
        float a0 = b_d[grow], a1 = a0, a2 = a0, a3 = a0;
        #pragma unroll 4
        for (int k = 0; k < HH; ++k) {
            float ww = g_Wihd2[((int)rank * 64 + k) * 256 + lr];
            a0 = fmaf(ww, hesm[(b4 + 0) * 64 + k], a0);
            a1 = fmaf(ww, hesm[(b4 + 1) * 64 + k], a1);
            a2 = fmaf(ww, hesm[(b4 + 2) * 64 + k], a2);
            a3 = fmaf(ww, hesm[(b4 + 3) * 64 + k], a3);
        }
        *(float4*)&xp[lr * 8 + b4] = make_float4(a0, a1, a2, a3);
    }
    __syncthreads();
    CLUSTER_SYNC();            // mbarrier init + h0 buffers visible cluster-wide

    const int gr = l >> 2, gc = l & 3;
    const int wbase = w * 16;
    const int ej = tid & 63, ebb = tid >> 6;
    float creg = 0.0f;

    unsigned hU = (unsigned)__cvta_generic_to_shared(hsm);
    unsigned remBase, remMbar;
    asm("mapa.shared::cluster.u32 %0, %1, %2;" : "=r"(remBase) : "r"(hU), "r"(rank ^ 1u));
    asm("mapa.shared::cluster.u32 %0, %1, %2;" : "=r"(remMbar) : "r"(mbar), "r"(rank ^ 1u));
    const unsigned myoff = (unsigned)(((koff + ej) * 8 + ebb) * 4);

    for (int t = 0; t < TT; ++t) {
        const float* hr = hsm + (((t & 1) ^ 1) << 10);
        const int wb = (t & 1) << 10;

        float2 x01 = *(const float2*)&xp[(wbase + gr) * 8 + 2 * gc];
        float2 x23 = *(const float2*)&xp[(wbase + gr + 8) * 8 + 2 * gc];
        float dd[4] = {x01.x, x01.y, x23.x, x23.y};
        float ee[4] = {0.f, 0.f, 0.f, 0.f};

        #pragma unroll
        for (int kt = 0; kt < 16; ++kt) {
            float b0 = hr[(kt * 8 + gc) * 8 + gr];
            float b1 = hr[(kt * 8 + gc + 4) * 8 + gr];
            mma_tf32((kt & 1) ? ee : dd,
                     __float_as_uint(af[kt].x), __float_as_uint(af[kt].y),
                     __float_as_uint(af[kt].z), __float_as_uint(af[kt].w),
                     __float_as_uint(b0), __float_as_uint(b1));
        }
        *(float2*)&gsm[(wbase + gr) * 10 + 2 * gc]     = make_float2(dd[0] + ee[0], dd[1] + ee[1]);
        *(float2*)&gsm[(wbase + gr + 8) * 10 + 2 * gc] = make_float2(dd[2] + ee[2], dd[3] + ee[3]);
        __syncthreads();       // local gate halves visible (no cross-CTA gate exchange here)

        float gi = gsm[(ej)       * 10 + ebb];
        float gf = gsm[(64 + ej)  * 10 + ebb];
        float gg = gsm[(128 + ej) * 10 + ebb];
        float go = gsm[(192 + ej) * 10 + ebb];
        float i_ = sig_ap(gi), f_ = sig_ap(gf), g_ = tanh_ap(gg), o_ = sig_ap(go);
        creg = f_ * creg + i_ * g_;
        float h_ = o_ * tanh_ap(creg);
        out[((size_t)(bb + ebb) * TT + t) * DD + koff + ej] = h_;

        float hrd = __uint_as_float(tf32r(h_));
        hsm[wb + (koff + ej) * 8 + ebb] = hrd;
        asm volatile("st.shared::cluster.f32 [%0], %1;"
                     :: "r"(remBase + (unsigned)(wb * 4) + myoff), "f"(hrd) : "memory");
        MBAR_ARRIVE_LOCAL(mbar);          // orders my local h store
        MBAR_ARRIVE_REMOTE(remMbar);      // release.cluster: orders my DSMEM h store
        MBAR_WAIT_CLUSTER(mbar, (unsigned)(t & 1));   // full h_t assembled in my hsm
    }
    CLUSTER_SYNC();            // keep peer alive until both CTAs are done
}

// ---------------- launch ----------------
extern "C" void kernel_launch(void* const* d_in, const int* in_sizes, int n_in,
                              void* d_out, int out_size) {
    const float* x     = (const float*)d_in[0];
    const float* Wih_e = (const float*)d_in[1];
    const float* Whh_e = (const float*)d_in[2];
    const float* b_e   = (const float*)d_in[3];
    const float* Wih_d = (const float*)d_in[4];
    const float* Whh_d = (const float*)d_in[5];
    const float* b_d   = (const float*)d_in[6];
    float* out = (float*)d_out;

    cudaFuncSetAttribute(enc_kernel, cudaFuncAttributeMaxDynamicSharedMemorySize, ENC_SMEM_BYTES);
    cudaFuncSetAttribute(dec_kernel, cudaFuncAttributeMaxDynamicSharedMemorySize, DEC_SMEM_BYTES);

    prep_kernel<<<576, 256>>>(Wih_e, Whh_e, Whh_d, Wih_d);
    enc_kernel<<<BATCH / 8 * 2, 256, ENC_SMEM_BYTES>>>(x, b_e);   // 128 CTAs = 64 clusters
    dec_kernel<<<BATCH / 8 * 2, 512, DEC_SMEM_BYTES>>>(b_d, out); // 128 CTAs = 64 clusters
}